// round 7
// baseline (speedup 1.0000x reference)
#include <cuda_runtime.h>
#include <math.h>

#define BS      4096
#define NE      6
#define D_FRAME 1830
#define D_I     1027
#define D_HH    512
#define D_P     2086
#define D_HEAD  1830   // 330 + 3 + 297 + 1200 packed head output

// ---------------- scratch (static device memory; no allocation) ----------------
__device__ float g_h0  [BS * D_P];      // [frame_prev (1830) | I_feat (256)]
__device__ float g_Iin [BS * D_I];
__device__ float g_t1  [BS * 256];
__device__ float g_t2  [BS * 256];
__device__ float g_g1  [BS * 512];
__device__ float g_g2  [BS * 256];
__device__ float g_om  [BS * NE];
__device__ float g_ha  [BS * D_HH];
__device__ float g_hb  [BS * D_HH];
__device__ float g_Wc  [D_HH * D_HEAD];
__device__ float g_bc  [D_HEAD];
__device__ float g_head[BS * D_HEAD];

// ---------------- helpers ----------------
__device__ __forceinline__ float eluf(float x) { return x > 0.f ? x : expm1f(x); }

__device__ __forceinline__ unsigned long long ffma2(unsigned long long a,
                                                    unsigned long long b,
                                                    unsigned long long c) {
    unsigned long long d;
    asm("fma.rn.f32x2 %0, %1, %2, %3;" : "=l"(d) : "l"(a), "l"(b), "l"(c));
    return d;
}
__device__ __forceinline__ unsigned long long dup2(float b) {
    unsigned long long r;
    asm("mov.b64 %0, {%1, %1};" : "=l"(r) : "f"(b));
    return r;
}
__device__ __forceinline__ void unpack2(unsigned long long v, float& lo, float& hi) {
    asm("mov.b64 {%0, %1}, %2;" : "=f"(lo), "=f"(hi) : "l"(v));
}

// ---------------- input assembly ----------------
__global__ void build_frame(const float* __restrict__ ppr,
                            const float* __restrict__ transl,
                            const float* __restrict__ verts,
                            const float* __restrict__ dists)
{
    int idx = blockIdx.x * blockDim.x + threadIdx.x;
    if (idx >= BS * D_FRAME) return;
    int b = idx / D_FRAME;
    int c = idx - b * D_FRAME;
    float v;
    if (c < 330) {
        int j = c / 6, r = c - j * 6;
        int map = r + (r >> 1);            // 0,1,3,4,6,7
        v = ppr[b * 495 + j * 9 + map];
    } else if (c < 333) {
        v = transl[b * 3 + (c - 330)];
    } else if (c < 1533) {
        v = verts[b * 1200 + (c - 333)];
    } else {
        v = dists[b * 297 + (c - 1533)];
    }
    g_h0[b * D_P + c] = v;
}

__global__ void build_iin(const float* __restrict__ bps,
                          const float* __restrict__ ogt)
{
    int idx = blockIdx.x * blockDim.x + threadIdx.x;
    if (idx >= BS * D_I) return;
    int b = idx / D_I;
    int c = idx - b * D_I;
    g_Iin[idx] = (c < 1024) ? bps[b * 1024 + c] : ogt[b * 3 + (c - 1024)];
}

// ---------------- pipelined GEMM: C = act(A @ B + bias) ----------------
// BM=128, BN=64, BK=16, 256 threads. Micro-tile 4(M) x 8(N) as 2 f32x2 pairs.
// Register-prefetch + double-buffered smem: LDG for tile i+1 issued during
// compute of tile i; single __syncthreads per iteration.
#define GBM 128
#define GBN 64
#define GBK 16
#define GNT 256

// per-thread load counts
#define LA 8   // BM*BK/GNT
#define LB 4   // BK*BN/GNT

__global__ __launch_bounds__(GNT)
void gemm_bias_act(const float* __restrict__ A, int lda,
                   const float* __restrict__ B,
                   const float* __restrict__ bias,
                   float* __restrict__ C, int ldc,
                   int N, int K, int act)
{
    __shared__ __align__(16) float As[2][GBK][GBM + 2];
    __shared__ __align__(16) float Bs[2][GBK][GBN];

    const int t  = threadIdx.x;
    const int tx = t & 7;       // 8 col-groups x 8 N
    const int ty = t >> 3;      // 32 row-groups x 4 M
    const int m0 = blockIdx.y * GBM;
    const int n0 = blockIdx.x * GBN;
    const int nIter = (K + GBK - 1) / GBK;

    float rA[LA], rB[LB];

    // prologue: load tile 0 -> regs
#pragma unroll
    for (int i = 0; i < LA; i++) {
        int l = i * GNT + t;
        int kg = l & 15;
        rA[i] = (kg < K) ? A[(m0 + (l >> 4)) * lda + kg] : 0.f;
    }
#pragma unroll
    for (int i = 0; i < LB; i++) {
        int l = i * GNT + t;
        int n = l & 63, kg = l >> 6;
        int ng = n0 + n;
        rB[i] = (kg < K && ng < N) ? B[kg * N + ng] : 0.f;
    }
    // stage tile 0 -> buf 0
#pragma unroll
    for (int i = 0; i < LA; i++) {
        int l = i * GNT + t;
        As[0][l & 15][l >> 4] = rA[i];
    }
#pragma unroll
    for (int i = 0; i < LB; i++) {
        int l = i * GNT + t;
        Bs[0][l >> 6][l & 63] = rB[i];
    }
    __syncthreads();

    // prefetch tile 1 -> regs (in flight across iter 0 compute)
    if (nIter > 1) {
        int kk = GBK;
#pragma unroll
        for (int i = 0; i < LA; i++) {
            int l = i * GNT + t;
            int kg = kk + (l & 15);
            rA[i] = (kg < K) ? A[(m0 + (l >> 4)) * lda + kg] : 0.f;
        }
#pragma unroll
        for (int i = 0; i < LB; i++) {
            int l = i * GNT + t;
            int kg = kk + (l >> 6), ng = n0 + (l & 63);
            rB[i] = (kg < K && ng < N) ? B[kg * N + ng] : 0.f;
        }
    }

    unsigned long long acc[2][8];
#pragma unroll
    for (int p = 0; p < 2; p++)
#pragma unroll
        for (int j = 0; j < 8; j++) acc[p][j] = 0ull;

    for (int it = 0; it < nIter; ++it) {
        int buf = it & 1;
        // stage prefetched tile it+1 into the other buffer (waits on its LDGs)
        if (it + 1 < nIter) {
#pragma unroll
            for (int i = 0; i < LA; i++) {
                int l = i * GNT + t;
                As[buf ^ 1][l & 15][l >> 4] = rA[i];
            }
#pragma unroll
            for (int i = 0; i < LB; i++) {
                int l = i * GNT + t;
                Bs[buf ^ 1][l >> 6][l & 63] = rB[i];
            }
        }
        // issue LDGs for tile it+2
        if (it + 2 < nIter) {
            int kk = (it + 2) * GBK;
#pragma unroll
            for (int i = 0; i < LA; i++) {
                int l = i * GNT + t;
                int kg = kk + (l & 15);
                rA[i] = (kg < K) ? A[(m0 + (l >> 4)) * lda + kg] : 0.f;
            }
#pragma unroll
            for (int i = 0; i < LB; i++) {
                int l = i * GNT + t;
                int kg = kk + (l >> 6), ng = n0 + (l & 63);
                rB[i] = (kg < K && ng < N) ? B[kg * N + ng] : 0.f;
            }
        }
        // compute current buffer
#pragma unroll
        for (int k = 0; k < GBK; k++) {
            unsigned long long a2[2];
            a2[0] = *(const unsigned long long*)&As[buf][k][ty * 4];
            a2[1] = *(const unsigned long long*)&As[buf][k][ty * 4 + 2];
            float4 b0 = *(const float4*)&Bs[buf][k][tx * 8];
            float4 b1 = *(const float4*)&Bs[buf][k][tx * 8 + 4];
            float bv[8] = {b0.x, b0.y, b0.z, b0.w, b1.x, b1.y, b1.z, b1.w};
#pragma unroll
            for (int j = 0; j < 8; j++) {
                unsigned long long bb = dup2(bv[j]);
                acc[0][j] = ffma2(a2[0], bb, acc[0][j]);
                acc[1][j] = ffma2(a2[1], bb, acc[1][j]);
            }
        }
        __syncthreads();
    }

#pragma unroll
    for (int p = 0; p < 2; p++) {
        int m = m0 + ty * 4 + 2 * p;
#pragma unroll
        for (int j = 0; j < 8; j++) {
            int n = n0 + tx * 8 + j;
            if (n < N) {
                float lo, hi;
                unpack2(acc[p][j], lo, hi);
                float bsv = bias[n];
                lo += bsv; hi += bsv;
                if (act) { lo = eluf(lo); hi = eluf(hi); }
                C[m * ldc + n]       = lo;
                C[(m + 1) * ldc + n] = hi;
            }
        }
    }
}

// ---------------- pipelined MoE GEMM over stacked experts ----------------
// C[b,n] = elu( sum_e om[b,e]*(A[b,:]@W_e)[n] + sum_e om[b,e]*eb[e,n] ),
// single GEMM with K_tot = NE*Kper; A scaled on the fly by om[b,e].
__global__ __launch_bounds__(GNT)
void moe_gemm(const float* __restrict__ A, int lda,
              const float* __restrict__ W,     // (NE*Kper, N) contiguous
              const float* __restrict__ eb,    // (NE, N)
              const float* __restrict__ om,    // (BS, NE)
              float* __restrict__ C,
              int N, int Kper)
{
    __shared__ __align__(16) float As[2][GBK][GBM + 2];
    __shared__ __align__(16) float Bs[2][GBK][GBN];
    __shared__ float om_s[GBM * NE];

    const int t  = threadIdx.x;
    const int tx = t & 7;
    const int ty = t >> 3;
    const int m0 = blockIdx.y * GBM;
    const int n0 = blockIdx.x * GBN;
    const int Ktot = NE * Kper;
    const int nIter = (Ktot + GBK - 1) / GBK;

    for (int i = t; i < GBM * NE; i += GNT) om_s[i] = om[m0 * NE + i];
    __syncthreads();

    float rA[LA], rB[LB];

    // tile loader (A side with expert decode + omega scaling)
    auto loadA = [&](int kk) {
        int e0 = kk / Kper;
        int r0 = kk - e0 * Kper;
#pragma unroll
        for (int i = 0; i < LA; i++) {
            int l = i * GNT + t;
            int m = l >> 4, k = l & 15;
            int kg = kk + k;
            float v = 0.f;
            if (kg < Ktot) {
                int e = e0, ii = r0 + k;
                if (ii >= Kper) { ii -= Kper; e++; }
                v = A[(m0 + m) * lda + ii] * om_s[m * NE + e];
            }
            rA[i] = v;
        }
    };
    auto loadB = [&](int kk) {
#pragma unroll
        for (int i = 0; i < LB; i++) {
            int l = i * GNT + t;
            int kg = kk + (l >> 6), ng = n0 + (l & 63);
            rB[i] = (kg < Ktot && ng < N) ? W[kg * N + ng] : 0.f;
        }
    };

    loadA(0); loadB(0);
#pragma unroll
    for (int i = 0; i < LA; i++) {
        int l = i * GNT + t;
        As[0][l & 15][l >> 4] = rA[i];
    }
#pragma unroll
    for (int i = 0; i < LB; i++) {
        int l = i * GNT + t;
        Bs[0][l >> 6][l & 63] = rB[i];
    }
    __syncthreads();
    if (nIter > 1) { loadA(GBK); loadB(GBK); }

    unsigned long long acc[2][8];
#pragma unroll
    for (int p = 0; p < 2; p++)
#pragma unroll
        for (int j = 0; j < 8; j++) acc[p][j] = 0ull;

    for (int it = 0; it < nIter; ++it) {
        int buf = it & 1;
        if (it + 1 < nIter) {
#pragma unroll
            for (int i = 0; i < LA; i++) {
                int l = i * GNT + t;
                As[buf ^ 1][l & 15][l >> 4] = rA[i];
            }
#pragma unroll
            for (int i = 0; i < LB; i++) {
                int l = i * GNT + t;
                Bs[buf ^ 1][l >> 6][l & 63] = rB[i];
            }
        }
        if (it + 2 < nIter) { loadA((it + 2) * GBK); loadB((it + 2) * GBK); }
#pragma unroll
        for (int k = 0; k < GBK; k++) {
            unsigned long long a2[2];
            a2[0] = *(const unsigned long long*)&As[buf][k][ty * 4];
            a2[1] = *(const unsigned long long*)&As[buf][k][ty * 4 + 2];
            float4 b0 = *(const float4*)&Bs[buf][k][tx * 8];
            float4 b1 = *(const float4*)&Bs[buf][k][tx * 8 + 4];
            float bv[8] = {b0.x, b0.y, b0.z, b0.w, b1.x, b1.y, b1.z, b1.w};
#pragma unroll
            for (int j = 0; j < 8; j++) {
                unsigned long long bb = dup2(bv[j]);
                acc[0][j] = ffma2(a2[0], bb, acc[0][j]);
                acc[1][j] = ffma2(a2[1], bb, acc[1][j]);
            }
        }
        __syncthreads();
    }

#pragma unroll
    for (int p = 0; p < 2; p++) {
        int ml = ty * 4 + 2 * p;
        int m  = m0 + ml;
#pragma unroll
        for (int j = 0; j < 8; j++) {
            int n = n0 + tx * 8 + j;
            if (n < N) {
                float lo, hi;
                unpack2(acc[p][j], lo, hi);
                float blo = 0.f, bhi = 0.f;
#pragma unroll
                for (int e = 0; e < NE; e++) {
                    float ev = eb[e * N + n];
                    blo += om_s[ml * NE + e] * ev;
                    bhi += om_s[(ml + 1) * NE + e] * ev;
                }
                C[m * N + n]       = eluf(lo + blo);
                C[(m + 1) * N + n] = eluf(hi + bhi);
            }
        }
    }
}

// ---------------- gating layer 3 + softmax (K=256, N=6) ----------------
__global__ void gate3_softmax(const float* __restrict__ g2,
                              const float* __restrict__ gw3,
                              const float* __restrict__ gb3,
                              float* __restrict__ om)
{
    int gwarp = (blockIdx.x * blockDim.x + threadIdx.x) >> 5;
    int lane  = threadIdx.x & 31;
    if (gwarp >= BS) return;
    float s[NE] = {0, 0, 0, 0, 0, 0};
    for (int k = lane; k < 256; k += 32) {
        float v = g2[gwarp * 256 + k];
#pragma unroll
        for (int o = 0; o < NE; o++) s[o] += v * gw3[k * NE + o];
    }
#pragma unroll
    for (int o = 0; o < NE; o++)
#pragma unroll
        for (int off = 16; off; off >>= 1)
            s[o] += __shfl_xor_sync(0xffffffffu, s[o], off);
    if (lane == 0) {
        float mx = -1e30f;
#pragma unroll
        for (int o = 0; o < NE; o++) { s[o] += gb3[o]; mx = fmaxf(mx, s[o]); }
        float sum = 0.f;
#pragma unroll
        for (int o = 0; o < NE; o++) { s[o] = expf(s[o] - mx); sum += s[o]; }
        float inv = 1.f / sum;
#pragma unroll
        for (int o = 0; o < NE; o++) om[gwarp * NE + o] = s[o] * inv;
    }
}

// ---------------- pack 4 head weight matrices into one (512 x 1830) ----------------
__global__ void pack_heads(const float* __restrict__ pw, const float* __restrict__ pb,
                           const float* __restrict__ tw, const float* __restrict__ tb,
                           const float* __restrict__ dw, const float* __restrict__ db,
                           const float* __restrict__ vw, const float* __restrict__ vb)
{
    int idx = blockIdx.x * blockDim.x + threadIdx.x;
    if (idx >= D_HH * D_HEAD) return;
    int k = idx / D_HEAD;
    int n = idx - k * D_HEAD;
    float w;
    if      (n < 330) w = pw[k * 330 + n];
    else if (n < 333) w = tw[k * 3 + (n - 330)];
    else if (n < 630) w = dw[k * 297 + (n - 333)];
    else              w = vw[k * 1200 + (n - 630)];
    g_Wc[idx] = w;
    if (idx < D_HEAD) {
        float b;
        if      (idx < 330) b = pb[idx];
        else if (idx < 333) b = tb[idx - 330];
        else if (idx < 630) b = db[idx - 333];
        else                b = vb[idx - 630];
        g_bc[idx] = b;
    }
}

// ---------------- finalize: crot2rotmat + scatter to output layout ----------------
__global__ void finalize(float* __restrict__ out)
{
    const int b   = blockIdx.x;
    const int tid = threadIdx.x;
    const float* h = &g_head[b * D_HEAD];
    const long long T0 = (long long)BS * 495;
    const long long D0 = T0 + (long long)BS * 3;
    const long long V0 = D0 + (long long)BS * 297;

    if (tid < 55) {
        const float* p = h + tid * 6;
        float a1x = p[0], a2x = p[1];
        float a1y = p[2], a2y = p[3];
        float a1z = p[4], a2z = p[5];
        float inv1 = 1.f / sqrtf(a1x * a1x + a1y * a1y + a1z * a1z);
        float b1x = a1x * inv1, b1y = a1y * inv1, b1z = a1z * inv1;
        float d = b1x * a2x + b1y * a2y + b1z * a2z;
        float cx = a2x - d * b1x, cy = a2y - d * b1y, cz = a2z - d * b1z;
        float inv2 = 1.f / sqrtf(cx * cx + cy * cy + cz * cz);
        float b2x = cx * inv2, b2y = cy * inv2, b2z = cz * inv2;
        float b3x = b1y * b2z - b1z * b2y;
        float b3y = b1z * b2x - b1x * b2z;
        float b3z = b1x * b2y - b1y * b2x;
        float* o = out + (long long)b * 495 + tid * 9;
        o[0] = b1x; o[1] = b2x; o[2] = b3x;
        o[3] = b1y; o[4] = b2y; o[5] = b3y;
        o[6] = b1z; o[7] = b2z; o[8] = b3z;
    }
    for (int c = tid; c < 3; c += blockDim.x)
        out[T0 + (long long)b * 3 + c] = h[330 + c];
    for (int c = tid; c < 297; c += blockDim.x)
        out[D0 + (long long)b * 297 + c] = h[333 + c];
    for (int c = tid; c < 1200; c += blockDim.x)
        out[V0 + (long long)b * 1200 + c] = h[630 + c];
}

// ---------------- host launcher ----------------
extern "C" void kernel_launch(void* const* d_in, const int* in_sizes, int n_in,
                              void* d_out, int out_size)
{
    const float* ppr    = (const float*)d_in[0];
    const float* transl = (const float*)d_in[1];
    const float* verts  = (const float*)d_in[2];
    const float* dists  = (const float*)d_in[3];
    const float* bps    = (const float*)d_in[4];
    const float* ogt    = (const float*)d_in[5];
    const float* iw1 = (const float*)d_in[6];  const float* ib1 = (const float*)d_in[7];
    const float* iw2 = (const float*)d_in[8];  const float* ib2 = (const float*)d_in[9];
    const float* iw3 = (const float*)d_in[10]; const float* ib3 = (const float*)d_in[11];
    const float* gw1 = (const float*)d_in[12]; const float* gb1 = (const float*)d_in[13];
    const float* gw2 = (const float*)d_in[14]; const float* gb2 = (const float*)d_in[15];
    const float* gw3 = (const float*)d_in[16]; const float* gb3 = (const float*)d_in[17];
    const float* ew1 = (const float*)d_in[18]; const float* eb1 = (const float*)d_in[19];
    const float* ew2 = (const float*)d_in[20]; const float* eb2 = (const float*)d_in[21];
    const float* ew3 = (const float*)d_in[22]; const float* eb3 = (const float*)d_in[23];
    const float* pw  = (const float*)d_in[24]; const float* pb  = (const float*)d_in[25];
    const float* tw  = (const float*)d_in[26]; const float* tb  = (const float*)d_in[27];
    const float* vw  = (const float*)d_in[28]; const float* vb  = (const float*)d_in[29];
    const float* dw  = (const float*)d_in[30]; const float* db  = (const float*)d_in[31];
    float* out = (float*)d_out;

    float *h0, *Iin, *t1, *t2, *g1, *g2, *om, *ha, *hb, *Wc, *bc, *head;
    cudaGetSymbolAddress((void**)&h0,   g_h0);
    cudaGetSymbolAddress((void**)&Iin,  g_Iin);
    cudaGetSymbolAddress((void**)&t1,   g_t1);
    cudaGetSymbolAddress((void**)&t2,   g_t2);
    cudaGetSymbolAddress((void**)&g1,   g_g1);
    cudaGetSymbolAddress((void**)&g2,   g_g2);
    cudaGetSymbolAddress((void**)&om,   g_om);
    cudaGetSymbolAddress((void**)&ha,   g_ha);
    cudaGetSymbolAddress((void**)&hb,   g_hb);
    cudaGetSymbolAddress((void**)&Wc,   g_Wc);
    cudaGetSymbolAddress((void**)&bc,   g_bc);
    cudaGetSymbolAddress((void**)&head, g_head);

    const int MB = BS / GBM;  // 32 row-blocks

    build_frame<<<(BS * D_FRAME + 255) / 256, 256>>>(ppr, transl, verts, dists);
    build_iin  <<<(BS * D_I + 255) / 256, 256>>>(bps, ogt);
    pack_heads <<<(D_HH * D_HEAD + 255) / 256, 256>>>(pw, pb, tw, tb, dw, db, vw, vb);

    // INet: 1027 -> 256 -> 256 -> 256 (last writes into h0 cols [1830,2086))
    gemm_bias_act<<<dim3(4, MB), GNT>>>(Iin, D_I, iw1, ib1, t1, 256, 256, D_I, 1);
    gemm_bias_act<<<dim3(4, MB), GNT>>>(t1, 256, iw2, ib2, t2, 256, 256, 256, 1);
    gemm_bias_act<<<dim3(4, MB), GNT>>>(t2, 256, iw3, ib3, h0 + D_FRAME, D_P, 256, 256, 1);

    // Gating: 1830 -> 512 -> 256 -> 6 + softmax
    gemm_bias_act<<<dim3(8, MB), GNT>>>(h0, D_P, gw1, gb1, g1, 512, 512, D_FRAME, 1);
    gemm_bias_act<<<dim3(4, MB), GNT>>>(g1, 512, gw2, gb2, g2, 256, 256, 512, 1);
    gate3_softmax<<<BS / 8, 256>>>(g2, gw3, gb3, om);

    // MoE trunk: 3 stacked-expert GEMMs
    moe_gemm<<<dim3(8, MB), GNT>>>(h0, D_P, ew1, eb1, om, ha, D_HH, D_P);
    moe_gemm<<<dim3(8, MB), GNT>>>(ha, D_HH, ew2, eb2, om, hb, D_HH, D_HH);
    moe_gemm<<<dim3(8, MB), GNT>>>(hb, D_HH, ew3, eb3, om, ha, D_HH, D_HH);

    // Fused heads: 4096 x 1830 = (4096 x 512) @ (512 x 1830)
    gemm_bias_act<<<dim3((D_HEAD + GBN - 1) / GBN, MB), GNT>>>(
        ha, D_HH, Wc, bc, head, D_HEAD, D_HEAD, D_HH, 0);

    finalize<<<BS, 128>>>(out);
}

// round 11
// speedup vs baseline: 1.0557x; 1.0557x over previous
#include <cuda_runtime.h>
#include <math.h>

#define BS      4096
#define NE      6
#define D_FRAME 1830
#define D_I     1027
#define D_HH    512
#define D_P     2086
#define D_HEAD  1830

// padded leading dims (multiples of 16 floats, 16B-aligned rows)
#define LDI 1056   // Iin:   1027 -> 1056
#define LDH 2112   // h0:    2086 -> 2112
#define LDW 1856   // Wc:    1830 -> 1856 (29 * 64)

typedef unsigned long long ull;

// ---------------- scratch (static device memory; no allocation) ----------------
__device__ float g_h0  [BS * LDH];
__device__ float g_Iin [BS * LDI];
__device__ float g_t1  [BS * 256];
__device__ float g_t2  [BS * 256];
__device__ float g_g1  [BS * 512];
__device__ float g_g2  [BS * 256];
__device__ float g_om  [BS * NE];
__device__ float g_ha  [BS * D_HH];
__device__ float g_hb  [BS * D_HH];
__device__ float g_Wc  [D_HH * LDW];
__device__ float g_bc  [D_HEAD];
__device__ float g_head[BS * D_HEAD];

// ---------------- helpers ----------------
__device__ __forceinline__ float eluf(float x) { return x > 0.f ? x : expm1f(x); }

__device__ __forceinline__ ull ffma2(ull a, ull b, ull c) {
    ull d;
    asm("fma.rn.f32x2 %0, %1, %2, %3;" : "=l"(d) : "l"(a), "l"(b), "l"(c));
    return d;
}
__device__ __forceinline__ ull dup2(float b) {
    ull r;
    asm("mov.b64 %0, {%1, %1};" : "=l"(r) : "f"(b));
    return r;
}
__device__ __forceinline__ void unpack2(ull v, float& lo, float& hi) {
    asm("mov.b64 {%0, %1}, %2;" : "=f"(lo), "=f"(hi) : "l"(v));
}
__device__ __forceinline__ void cpa16(unsigned dst, const float* src) {
    asm volatile("cp.async.cg.shared.global [%0], [%1], 16;" :: "r"(dst), "l"(src) : "memory");
}
__device__ __forceinline__ void cpa16z(unsigned dst, const float* src, int ok) {
    int sz = ok ? 16 : 0;   // src-size 0 -> zero-fill 16B
    asm volatile("cp.async.cg.shared.global [%0], [%1], 16, %2;" :: "r"(dst), "l"(src), "r"(sz) : "memory");
}
__device__ __forceinline__ void cpa_commit() {
    asm volatile("cp.async.commit_group;" ::: "memory");
}

// ---------------- input assembly (writes pads = 0) ----------------
__global__ void build_frame(const float* __restrict__ ppr,
                            const float* __restrict__ transl,
                            const float* __restrict__ verts,
                            const float* __restrict__ dists)
{
    // per batch: 1830 frame cols + 26 pad cols (2086..2111)
    int idx = blockIdx.x * blockDim.x + threadIdx.x;
    if (idx >= BS * (D_FRAME + (LDH - D_P))) return;
    int per = D_FRAME + (LDH - D_P);
    int b = idx / per;
    int c = idx - b * per;
    if (c >= D_FRAME) {                     // zero pad cols [2086, 2112)
        g_h0[b * LDH + D_P + (c - D_FRAME)] = 0.f;
        return;
    }
    float v;
    if (c < 330) {
        int j = c / 6, r = c - j * 6;
        int map = r + (r >> 1);             // 0,1,3,4,6,7
        v = ppr[b * 495 + j * 9 + map];
    } else if (c < 333) {
        v = transl[b * 3 + (c - 330)];
    } else if (c < 1533) {
        v = verts[b * 1200 + (c - 333)];
    } else {
        v = dists[b * 297 + (c - 1533)];
    }
    g_h0[b * LDH + c] = v;
}

__global__ void build_iin(const float* __restrict__ bps,
                          const float* __restrict__ ogt)
{
    int idx = blockIdx.x * blockDim.x + threadIdx.x;
    if (idx >= BS * LDI) return;
    int b = idx / LDI;
    int c = idx - b * LDI;
    float v = 0.f;
    if (c < 1024)      v = bps[b * 1024 + c];
    else if (c < D_I)  v = ogt[b * 3 + (c - 1024)];
    g_Iin[idx] = v;
}

// ---------------- cp.async pipelined GEMM ----------------
// BM=64, BN=64, BK=16, 128 threads, 3 stages.
// Micro-tile 4(M) x 8(N): acc pairs packed along N (f32x2), A scalar-dup.
#define BM  64
#define BN  64
#define BKK 16
#define NTH 128
#define NST 3
#define ASTR 20   // A smem row stride (floats), 16B aligned

__global__ __launch_bounds__(NTH)
void gemm_bias_act(const float* __restrict__ A, int lda,
                   const float* __restrict__ B, int ldb,
                   const float* __restrict__ bias,
                   float* __restrict__ C, int ldc,
                   int N, int K, int act)
{
    __shared__ __align__(16) float As[NST][BM][ASTR];
    __shared__ __align__(16) float Bs[NST][BKK][BN];

    const int t  = threadIdx.x;
    const int tx = t & 7;
    const int ty = t >> 3;
    const int m0 = blockIdx.y * BM;
    const int n0 = blockIdx.x * BN;
    const int nIter = (K + BKK - 1) / BKK;

    const int ar = t >> 2, ak = (t & 3) * 4;    // A: 2 chunks (rows ar, ar+32)
    const int bn = (t & 15) * 4, bk = t >> 4;   // B: 2 chunks (rows bk, bk+8)

    auto issue = [&](int it) {
        int kt = it * BKK;
        int st = it % NST;
#pragma unroll
        for (int i = 0; i < 2; i++) {
            int r = ar + 32 * i;
            unsigned d = (unsigned)__cvta_generic_to_shared(&As[st][r][ak]);
            cpa16(d, A + (size_t)(m0 + r) * lda + kt + ak);
        }
#pragma unroll
        for (int i = 0; i < 2; i++) {
            int kr = bk + 8 * i;
            int kg = kt + kr;
            unsigned d = (unsigned)__cvta_generic_to_shared(&Bs[st][kr][bn]);
            cpa16z(d, B + (size_t)kg * ldb + n0 + bn, kg < K);
        }
        cpa_commit();
    };

    issue(0);
    if (nIter > 1) issue(1);

    ull acc[4][4];
#pragma unroll
    for (int j = 0; j < 4; j++)
#pragma unroll
        for (int p = 0; p < 4; p++) acc[j][p] = 0ull;

    for (int it = 0; it < nIter; ++it) {
        if (it + 1 < nIter) asm volatile("cp.async.wait_group 1;" ::: "memory");
        else                asm volatile("cp.async.wait_group 0;" ::: "memory");
        __syncthreads();
        if (it + 2 < nIter) issue(it + 2);
        const int st = it % NST;
#pragma unroll
        for (int k4 = 0; k4 < 4; k4++) {
            float4 av[4];
#pragma unroll
            for (int j = 0; j < 4; j++)
                av[j] = *(const float4*)&As[st][ty * 4 + j][k4 * 4];
#pragma unroll
            for (int kk = 0; kk < 4; kk++) {
                const int k = k4 * 4 + kk;
                ulonglong2 b01 = *(const ulonglong2*)&Bs[st][k][tx * 8];
                ulonglong2 b23 = *(const ulonglong2*)&Bs[st][k][tx * 8 + 4];
                ull bb[4] = {b01.x, b01.y, b23.x, b23.y};
#pragma unroll
                for (int j = 0; j < 4; j++) {
                    ull ad = dup2(((const float*)&av[j])[kk]);
#pragma unroll
                    for (int p = 0; p < 4; p++)
                        acc[j][p] = ffma2(ad, bb[p], acc[j][p]);
                }
            }
        }
    }

#pragma unroll
    for (int j = 0; j < 4; j++) {
        int m = m0 + ty * 4 + j;
#pragma unroll
        for (int p = 0; p < 4; p++) {
            int n = n0 + tx * 8 + 2 * p;
            if (n < N) {
                float lo, hi;
                unpack2(acc[j][p], lo, hi);
                lo += bias[n]; hi += bias[n + 1];
                if (act) { lo = eluf(lo); hi = eluf(hi); }
                C[(size_t)m * ldc + n]     = lo;
                C[(size_t)m * ldc + n + 1] = hi;
            }
        }
    }
}

// ---------------- cp.async pipelined MoE GEMM ----------------
// Per-expert K-segments; expert partial accumulated in acc_e and folded
// into acc with omega at each expert boundary (exact reference math).
__global__ __launch_bounds__(NTH)
void moe_gemm(const float* __restrict__ A, int lda,
              const float* __restrict__ W,     // (NE*Kper, 512)
              const float* __restrict__ eb,    // (NE, 512)
              const float* __restrict__ om,    // (BS, NE)
              float* __restrict__ C,
              int Kper)
{
    __shared__ __align__(16) float As[NST][BM][ASTR];
    __shared__ __align__(16) float Bs[NST][BKK][BN];
    __shared__ float om_s[BM * NE];

    const int t  = threadIdx.x;
    const int tx = t & 7;
    const int ty = t >> 3;
    const int m0 = blockIdx.y * BM;
    const int n0 = blockIdx.x * BN;
    const int iPerE = (Kper + BKK - 1) / BKK;
    const int nIter = NE * iPerE;

    for (int i = t; i < BM * NE; i += NTH) om_s[i] = om[m0 * NE + i];

    const int ar = t >> 2, ak = (t & 3) * 4;
    const int bn = (t & 15) * 4, bk = t >> 4;

    auto issue = [&](int it) {
        int e  = it / iPerE;
        int kt = (it - e * iPerE) * BKK;
        int st = it % NST;
#pragma unroll
        for (int i = 0; i < 2; i++) {
            int r = ar + 32 * i;
            unsigned d = (unsigned)__cvta_generic_to_shared(&As[st][r][ak]);
            cpa16(d, A + (size_t)(m0 + r) * lda + kt + ak);
        }
#pragma unroll
        for (int i = 0; i < 2; i++) {
            int kr = bk + 8 * i;
            int kl = kt + kr;                          // local k within expert
            unsigned d = (unsigned)__cvta_generic_to_shared(&Bs[st][kr][bn]);
            cpa16z(d, W + (size_t)(e * Kper + kl) * 512 + n0 + bn, kl < Kper);
        }
        cpa_commit();
    };

    issue(0);
    if (nIter > 1) issue(1);

    ull acc[4][4], acce[4][4];
#pragma unroll
    for (int j = 0; j < 4; j++)
#pragma unroll
        for (int p = 0; p < 4; p++) { acc[j][p] = 0ull; acce[j][p] = 0ull; }

    int e = 0, cnt = 0;
    for (int it = 0; it < nIter; ++it) {
        if (it + 1 < nIter) asm volatile("cp.async.wait_group 1;" ::: "memory");
        else                asm volatile("cp.async.wait_group 0;" ::: "memory");
        __syncthreads();
        if (it + 2 < nIter) issue(it + 2);
        const int st = it % NST;
#pragma unroll
        for (int k4 = 0; k4 < 4; k4++) {
            float4 av[4];
#pragma unroll
            for (int j = 0; j < 4; j++)
                av[j] = *(const float4*)&As[st][ty * 4 + j][k4 * 4];
#pragma unroll
            for (int kk = 0; kk < 4; kk++) {
                const int k = k4 * 4 + kk;
                ulonglong2 b01 = *(const ulonglong2*)&Bs[st][k][tx * 8];
                ulonglong2 b23 = *(const ulonglong2*)&Bs[st][k][tx * 8 + 4];
                ull bb[4] = {b01.x, b01.y, b23.x, b23.y};
#pragma unroll
                for (int j = 0; j < 4; j++) {
                    ull ad = dup2(((const float*)&av[j])[kk]);
#pragma unroll
                    for (int p = 0; p < 4; p++)
                        acce[j][p] = ffma2(ad, bb[p], acce[j][p]);
                }
            }
        }
        if (++cnt == iPerE) {   // expert boundary: fold with omega
#pragma unroll
            for (int j = 0; j < 4; j++) {
                ull od = dup2(om_s[(ty * 4 + j) * NE + e]);
#pragma unroll
                for (int p = 0; p < 4; p++) {
                    acc[j][p] = ffma2(od, acce[j][p], acc[j][p]);
                    acce[j][p] = 0ull;
                }
            }
            e++; cnt = 0;
        }
    }

#pragma unroll
    for (int j = 0; j < 4; j++) {
        int m = m0 + ty * 4 + j;
#pragma unroll
        for (int p = 0; p < 4; p++) {
            int n = n0 + tx * 8 + 2 * p;
            ull v = acc[j][p];
#pragma unroll
            for (int ee = 0; ee < NE; ee++) {
                ull ebp = *(const ull*)&eb[ee * 512 + n];
                v = ffma2(dup2(om_s[(ty * 4 + j) * NE + ee]), ebp, v);
            }
            float lo, hi;
            unpack2(v, lo, hi);
            C[(size_t)m * 512 + n]     = eluf(lo);
            C[(size_t)m * 512 + n + 1] = eluf(hi);
        }
    }
}

// ---------------- gating layer 3 + softmax (K=256, N=6) ----------------
__global__ void gate3_softmax(const float* __restrict__ g2,
                              const float* __restrict__ gw3,
                              const float* __restrict__ gb3,
                              float* __restrict__ om)
{
    int gwarp = (blockIdx.x * blockDim.x + threadIdx.x) >> 5;
    int lane  = threadIdx.x & 31;
    if (gwarp >= BS) return;
    float s[NE] = {0, 0, 0, 0, 0, 0};
    for (int k = lane; k < 256; k += 32) {
        float v = g2[gwarp * 256 + k];
#pragma unroll
        for (int o = 0; o < NE; o++) s[o] += v * gw3[k * NE + o];
    }
#pragma unroll
    for (int o = 0; o < NE; o++)
#pragma unroll
        for (int off = 16; off; off >>= 1)
            s[o] += __shfl_xor_sync(0xffffffffu, s[o], off);
    if (lane == 0) {
        float mx = -1e30f;
#pragma unroll
        for (int o = 0; o < NE; o++) { s[o] += gb3[o]; mx = fmaxf(mx, s[o]); }
        float sum = 0.f;
#pragma unroll
        for (int o = 0; o < NE; o++) { s[o] = expf(s[o] - mx); sum += s[o]; }
        float inv = 1.f / sum;
#pragma unroll
        for (int o = 0; o < NE; o++) om[gwarp * NE + o] = s[o] * inv;
    }
}

// ---------------- pack head weights into (512 x LDW), zero pad ----------------
__global__ void pack_heads(const float* __restrict__ pw, const float* __restrict__ pb,
                           const float* __restrict__ tw, const float* __restrict__ tb,
                           const float* __restrict__ dw, const float* __restrict__ db,
                           const float* __restrict__ vw, const float* __restrict__ vb)
{
    int idx = blockIdx.x * blockDim.x + threadIdx.x;
    if (idx >= D_HH * LDW) return;
    int k = idx / LDW;
    int n = idx - k * LDW;
    float w = 0.f;
    if      (n < 330)    w = pw[k * 330 + n];
    else if (n < 333)    w = tw[k * 3 + (n - 330)];
    else if (n < 630)    w = dw[k * 297 + (n - 333)];
    else if (n < D_HEAD) w = vw[k * 1200 + (n - 630)];
    g_Wc[idx] = w;
    if (idx < D_HEAD) {
        float b;
        if      (idx < 330) b = pb[idx];
        else if (idx < 333) b = tb[idx - 330];
        else if (idx < 630) b = db[idx - 333];
        else                b = vb[idx - 630];
        g_bc[idx] = b;
    }
}

// ---------------- finalize: crot2rotmat + scatter ----------------
__global__ void finalize(float* __restrict__ out)
{
    const int b   = blockIdx.x;
    const int tid = threadIdx.x;
    const float* h = &g_head[b * D_HEAD];
    const long long T0 = (long long)BS * 495;
    const long long D0 = T0 + (long long)BS * 3;
    const long long V0 = D0 + (long long)BS * 297;

    if (tid < 55) {
        const float* p = h + tid * 6;
        float a1x = p[0], a2x = p[1];
        float a1y = p[2], a2y = p[3];
        float a1z = p[4], a2z = p[5];
        float inv1 = 1.f / sqrtf(a1x * a1x + a1y * a1y + a1z * a1z);
        float b1x = a1x * inv1, b1y = a1y * inv1, b1z = a1z * inv1;
        float d = b1x * a2x + b1y * a2y + b1z * a2z;
        float cx = a2x - d * b1x, cy = a2y - d * b1y, cz = a2z - d * b1z;
        float inv2 = 1.f / sqrtf(cx * cx + cy * cy + cz * cz);
        float b2x = cx * inv2, b2y = cy * inv2, b2z = cz * inv2;
        float b3x = b1y * b2z - b1z * b2y;
        float b3y = b1z * b2x - b1x * b2z;
        float b3z = b1x * b2y - b1y * b2x;
        float* o = out + (long long)b * 495 + tid * 9;
        o[0] = b1x; o[1] = b2x; o[2] = b3x;
        o[3] = b1y; o[4] = b2y; o[5] = b3y;
        o[6] = b1z; o[7] = b2z; o[8] = b3z;
    }
    for (int c = tid; c < 3; c += blockDim.x)
        out[T0 + (long long)b * 3 + c] = h[330 + c];
    for (int c = tid; c < 297; c += blockDim.x)
        out[D0 + (long long)b * 297 + c] = h[333 + c];
    for (int c = tid; c < 1200; c += blockDim.x)
        out[V0 + (long long)b * 1200 + c] = h[630 + c];
}

// ---------------- host launcher ----------------
extern "C" void kernel_launch(void* const* d_in, const int* in_sizes, int n_in,
                              void* d_out, int out_size)
{
    const float* ppr    = (const float*)d_in[0];
    const float* transl = (const float*)d_in[1];
    const float* verts  = (const float*)d_in[2];
    const float* dists  = (const float*)d_in[3];
    const float* bps    = (const float*)d_in[4];
    const float* ogt    = (const float*)d_in[5];
    const float* iw1 = (const float*)d_in[6];  const float* ib1 = (const float*)d_in[7];
    const float* iw2 = (const float*)d_in[8];  const float* ib2 = (const float*)d_in[9];
    const float* iw3 = (const float*)d_in[10]; const float* ib3 = (const float*)d_in[11];
    const float* gw1 = (const float*)d_in[12]; const float* gb1 = (const float*)d_in[13];
    const float* gw2 = (const float*)d_in[14]; const float* gb2 = (const float*)d_in[15];
    const float* gw3 = (const float*)d_in[16]; const float* gb3 = (const float*)d_in[17];
    const float* ew1 = (const float*)d_in[18]; const float* eb1 = (const float*)d_in[19];
    const float* ew2 = (const float*)d_in[20]; const float* eb2 = (const float*)d_in[21];
    const float* ew3 = (const float*)d_in[22]; const float* eb3 = (const float*)d_in[23];
    const float* pw  = (const float*)d_in[24]; const float* pb  = (const float*)d_in[25];
    const float* tw  = (const float*)d_in[26]; const float* tb  = (const float*)d_in[27];
    const float* vw  = (const float*)d_in[28]; const float* vb  = (const float*)d_in[29];
    const float* dw  = (const float*)d_in[30]; const float* db  = (const float*)d_in[31];
    float* out = (float*)d_out;

    float *h0, *Iin, *t1, *t2, *g1, *g2, *om, *ha, *hb, *Wc, *bc, *head;
    cudaGetSymbolAddress((void**)&h0,   g_h0);
    cudaGetSymbolAddress((void**)&Iin,  g_Iin);
    cudaGetSymbolAddress((void**)&t1,   g_t1);
    cudaGetSymbolAddress((void**)&t2,   g_t2);
    cudaGetSymbolAddress((void**)&g1,   g_g1);
    cudaGetSymbolAddress((void**)&g2,   g_g2);
    cudaGetSymbolAddress((void**)&om,   g_om);
    cudaGetSymbolAddress((void**)&ha,   g_ha);
    cudaGetSymbolAddress((void**)&hb,   g_hb);
    cudaGetSymbolAddress((void**)&Wc,   g_Wc);
    cudaGetSymbolAddress((void**)&bc,   g_bc);
    cudaGetSymbolAddress((void**)&head, g_head);

    const int MB = BS / BM;  // 64 row-blocks

    build_frame<<<(BS * (D_FRAME + (LDH - D_P)) + 255) / 256, 256>>>(ppr, transl, verts, dists);
    build_iin  <<<(BS * LDI + 255) / 256, 256>>>(bps, ogt);
    pack_heads <<<(D_HH * LDW + 255) / 256, 256>>>(pw, pb, tw, tb, dw, db, vw, vb);

    // INet: 1027 -> 256 -> 256 -> 256 (last writes into h0 cols [1830,2086))
    gemm_bias_act<<<dim3(4, MB), NTH>>>(Iin, LDI, iw1, 256, ib1, t1, 256, 256, D_I, 1);
    gemm_bias_act<<<dim3(4, MB), NTH>>>(t1, 256, iw2, 256, ib2, t2, 256, 256, 256, 1);
    gemm_bias_act<<<dim3(4, MB), NTH>>>(t2, 256, iw3, 256, ib3, h0 + D_FRAME, LDH, 256, 256, 1);

    // Gating: 1830 -> 512 -> 256 -> 6 + softmax
    gemm_bias_act<<<dim3(8, MB), NTH>>>(h0, LDH, gw1, 512, gb1, g1, 512, 512, D_FRAME, 1);
    gemm_bias_act<<<dim3(4, MB), NTH>>>(g1, 512, gw2, 256, gb2, g2, 256, 256, 512, 1);
    gate3_softmax<<<BS / 8, 256>>>(g2, gw3, gb3, om);

    // MoE trunk: 3 expert-segmented GEMMs
    moe_gemm<<<dim3(8, MB), NTH>>>(h0, LDH, ew1, eb1, om, ha, D_P);
    moe_gemm<<<dim3(8, MB), NTH>>>(ha, 512, ew2, eb2, om, hb, D_HH);
    moe_gemm<<<dim3(8, MB), NTH>>>(hb, 512, ew3, eb3, om, ha, D_HH);

    // Fused heads: (4096 x 512) @ (512 x 1830)
    gemm_bias_act<<<dim3(LDW / BN, MB), NTH>>>(ha, 512, Wc, LDW, bc, head, D_HEAD, D_HEAD, 512, 0);

    finalize<<<BS, 128>>>(out);
}